// round 1
// baseline (speedup 1.0000x reference)
#include <cuda_runtime.h>

#define FEATURE_COUNT (2LL * 64 * ((6 + 6 + 1) * 64))   // 106496
#define ACCUM 256
#define LEAK 0.1f

// ---------------------------------------------------------------------------
// int64-vs-int32 detection for the integer input arrays.
// The reference requests jnp.int64; depending on JAX x64 config the harness
// may hand us int32. Sample 16 values interpreted as int64: valid feature
// indices are in [0, FEATURE_COUNT). If the data is really int32, the int64
// reinterpretation packs two random indices per word -> astronomically
// unlikely to all land in range. Deterministic given fixed inputs.
// ---------------------------------------------------------------------------
__device__ int g_is64;

__global__ void detect_dtype_kernel(const void* __restrict__ idx) {
    if (threadIdx.x == 0 && blockIdx.x == 0) {
        const long long* p = (const long long*)idx;
        int ok = 1;
        #pragma unroll
        for (int k = 0; k < 16; k++) {
            long long v = p[k];
            if (v < 0 || v >= FEATURE_COUNT) ok = 0;
        }
        g_is64 = ok;
    }
}

__device__ __forceinline__ long long geti(const void* p, long long i, int is64) {
    return is64 ? ((const long long*)p)[i] : (long long)((const int*)p)[i];
}

__device__ __forceinline__ float clipped_relu(float x) {
    float c = fminf(fmaxf(x, -1.0f), 127.0f / 128.0f);
    return c + LEAK * (x - c);
}

// ---------------------------------------------------------------------------
// Main kernel: 256 threads = 4 groups of 64; each group handles one batch.
// Each thread owns 4 accumulator columns (float4). Gather-sum 32 rows of
// 1KB each (coalesced LDG.128), then the selected model's tiny MLP.
// ---------------------------------------------------------------------------
__global__ __launch_bounds__(256) void nnue_kernel(
    const void*  __restrict__ indices,
    const void*  __restrict__ offsets,
    const void*  __restrict__ which_model,
    const void*  __restrict__ lengths,
    const float* __restrict__ embed,
    const float* __restrict__ bias,
    const float* __restrict__ W1, const float* __restrict__ b1,
    const float* __restrict__ W2, const float* __restrict__ b2,
    const float* __restrict__ W3, const float* __restrict__ b3,
    float* __restrict__ out,
    long long n_idx, int B)
{
    __shared__ float4 s_emb[4][64];   // activated accumulator, 256 f32 per group
    __shared__ float  s_h1[4][16];
    __shared__ float  s_psqt[4];
    __shared__ int    s_sel[4];

    const int tid  = threadIdx.x;
    const int g    = tid >> 6;        // group 0..3
    const int lane = tid & 63;        // 0..63, owns columns [4*lane, 4*lane+4)
    const int b    = blockIdx.x * 4 + g;
    const bool active = (b < B);
    const int is64 = g_is64;

    // ---- segment bounds ----
    long long lo = 0, hi = 0;
    if (active) {
        lo = geti(offsets, b, is64);
        hi = (b + 1 < B) ? geti(offsets, b + 1, is64) : n_idx;
    }

    // ---- model selection (sel = which_model + (lengths/17)*4) ----
    if (lane == 0) {
        int sel = 0;
        if (active) {
            int wm = (int)geti(which_model, b, is64);
            int le = (int)geti(lengths, b, is64);
            sel = wm + (le / 17) * 4;
        }
        s_sel[g] = sel;
    }

    // ---- gather-sum ----
    const float4* __restrict__ E4 = (const float4*)embed;
    float4 acc = ((const float4*)bias)[lane];
    long long cnt = hi - lo;
    if (cnt == 32) {
        // fast path: unroll 8 -> 8 independent row loads in flight
        #pragma unroll
        for (int t = 0; t < 32; t += 8) {
            long long id[8];
            #pragma unroll
            for (int u = 0; u < 8; u++) id[u] = geti(indices, lo + t + u, is64);
            #pragma unroll
            for (int u = 0; u < 8; u++) {
                float4 v = E4[id[u] * 64 + lane];
                acc.x += v.x; acc.y += v.y; acc.z += v.z; acc.w += v.w;
            }
        }
    } else {
        for (long long j = lo; j < hi; j++) {
            float4 v = E4[geti(indices, j, is64) * 64 + lane];
            acc.x += v.x; acc.y += v.y; acc.z += v.z; acc.w += v.w;
        }
    }

    if (lane == 0) s_psqt[g] = acc.x;   // psqt = pre-activation column 0
    s_emb[g][lane] = make_float4(clipped_relu(acc.x), clipped_relu(acc.y),
                                 clipped_relu(acc.z), clipped_relu(acc.w));
    __syncthreads();

    // ---- layer 1: h1[o] = cr( dot(emb, W1[sel][o]) + b1[sel][o] ), o<16 ----
    {
        const int sel = s_sel[g];
        const int o = lane >> 2;       // 16 outputs, 4 lanes each
        const int k = lane & 3;        // each lane sums 64 of 256 elements
        const float4* __restrict__ w = (const float4*)(W1 + ((long long)sel * 16 + o) * ACCUM) + k * 16;
        const float4* __restrict__ e = &s_emb[g][0] + k * 16;
        float s = 0.0f;
        #pragma unroll
        for (int j = 0; j < 16; j++) {
            float4 wv = w[j], ev = e[j];
            s += wv.x * ev.x + wv.y * ev.y + wv.z * ev.z + wv.w * ev.w;
        }
        s += __shfl_xor_sync(0xffffffffu, s, 1);
        s += __shfl_xor_sync(0xffffffffu, s, 2);
        if (k == 0) s_h1[g][o] = clipped_relu(s + b1[sel * 16 + o]);
    }
    __syncthreads();

    // ---- layers 2+3 + epilogue (first warp of each group) ----
    if (lane < 32) {
        const int sel = s_sel[g];
        const int o = lane;            // 32 hidden units
        const float* __restrict__ w2 = W2 + ((long long)sel * 32 + o) * 16;
        float s = b2[sel * 32 + o];
        #pragma unroll
        for (int j = 0; j < 16; j++) s += w2[j] * s_h1[g][j];
        float h2 = clipped_relu(s);
        float p = h2 * W3[sel * 32 + o];
        #pragma unroll
        for (int off = 16; off > 0; off >>= 1)
            p += __shfl_xor_sync(0xffffffffu, p, off);
        if (o == 0 && active)
            out[b] = tanhf(p + b3[sel] + s_psqt[g]);
    }
}

extern "C" void kernel_launch(void* const* d_in, const int* in_sizes, int n_in,
                              void* d_out, int out_size) {
    const void*  indices     = d_in[0];
    const void*  offsets     = d_in[1];
    const void*  which_model = d_in[2];
    const void*  lengths     = d_in[3];
    const float* embed       = (const float*)d_in[4];
    const float* bias        = (const float*)d_in[5];
    const float* W1 = (const float*)d_in[6];
    const float* b1 = (const float*)d_in[7];
    const float* W2 = (const float*)d_in[8];
    const float* b2 = (const float*)d_in[9];
    const float* W3 = (const float*)d_in[10];
    const float* b3 = (const float*)d_in[11];

    long long n_idx = in_sizes[0];
    int B = in_sizes[1];

    detect_dtype_kernel<<<1, 1>>>(indices);
    nnue_kernel<<<(B + 3) / 4, 256>>>(indices, offsets, which_model, lengths,
                                      embed, bias, W1, b1, W2, b2, W3, b3,
                                      (float*)d_out, n_idx, B);
}